// round 8
// baseline (speedup 1.0000x reference)
#include <cuda_runtime.h>
#include <math.h>
#include <stdint.h>

// ---------------------------------------------------------------------------
//   gwc_feature (4,96,160,288)  concat_feature (4,12,160,288)
//   downsample: conv3x3 s2 p1 -> BN -> leaky(0.1) -> conv1x1 -> softmax(9)
//               -> weighted unfold sum   (HO=80, WO=144)
//   volume: D=24, gwc groups=8 (cpg=12), out (2, 32, 24, 80, 144) f32
// ---------------------------------------------------------------------------

#define HO_ 80
#define WO_ 144
#define HW_ (HO_*WO_)

// scratch (bss, no allocation)
static __device__ float g_y1   [4*192*HW_];
static __device__ float g_mask [4*144*HW_];
static __device__ float g_g8x  [4* 96*HW_];
static __device__ float g_cy1  [4* 24*HW_];
static __device__ float g_cmask[4*108*HW_];
static __device__ float g_c8x  [4* 12*HW_];

// Split (x0,x1) into packed bf16x2 hi and residual lo. Low k in low 16 bits.
__device__ __forceinline__ uint2 split2(float x0, float x1) {
    uint32_t h;
    asm("cvt.rn.bf16x2.f32 %0, %1, %2;" : "=r"(h) : "f"(x1), "f"(x0));
    const float h0 = __uint_as_float(h << 16);
    const float h1 = __uint_as_float(h & 0xffff0000u);
    uint32_t l;
    asm("cvt.rn.bf16x2.f32 %0, %1, %2;" : "=r"(l) : "f"(x1 - h1), "f"(x0 - h0));
    uint2 r; r.x = h; r.y = l; return r;
}

__device__ __forceinline__ void mma_bf16(float* c, const uint32_t* a, const uint32_t* b) {
    asm volatile(
        "mma.sync.aligned.m16n8k16.row.col.f32.bf16.bf16.f32 "
        "{%0,%1,%2,%3}, {%4,%5,%6,%7}, {%8,%9}, {%0,%1,%2,%3};"
        : "+f"(c[0]), "+f"(c[1]), "+f"(c[2]), "+f"(c[3])
        : "r"(a[0]), "r"(a[1]), "r"(a[2]), "r"(a[3]), "r"(b[0]), "r"(b[1]));
}

// ---------------------------------------------------------------------------
// Implicit-im2col GEMM on tensor cores, bf16 2-split (hh + hl + lh),
// fp32 accumulate. Compile-time shapes; K enumerated as (p = kh*3+kw, ic)
// so a BK=16 tile shares one spatial tap when CIN % 16 == 0 (hoisted
// validity + offset). Weights indexed w[oc*K + ic*KS*KS + p] (same order).
// Block 256 thr, tile 64(oc) x 128(pos), BK=16 (one m16n8k16 k-step).
// 8 warps as 2(M) x 4(N); warp tile 32x32 = 2x4 mma tiles.
// Requires HW % 128 == 0 (11520 ok), CIN even.
// ---------------------------------------------------------------------------
template<int KS, int CIN, int COUT, bool DO_BN>
__global__ void __launch_bounds__(256, 3)
conv_mma_kernel(
    const float* __restrict__ x, const float* __restrict__ w,
    const float* __restrict__ bn_g, const float* __restrict__ bn_b,
    const float* __restrict__ bn_m, const float* __restrict__ bn_v,
    float* __restrict__ out,
    int Hin, int Win, int Hout, int Wout)
{
    constexpr int K      = CIN * KS * KS;
    constexpr int KSKS   = KS * KS;
    constexpr int STRIDE = (KS == 3) ? 2 : 1;
    constexpr int PAD    = (KS == 3) ? 1 : 0;
    constexpr int NK     = (K + 15) >> 4;

    __shared__ __align__(16) uint2 Ap[2][8][68];   // [buf][kpair][oc]
    __shared__ __align__(16) uint2 Bp[2][8][132];  // [buf][kpair][pos]

    const int HW   = Hout * Wout;
    const int HWin = Hin * Win;
    const int bm = blockIdx.y * 64;
    const int bn = blockIdx.x * 128;
    const int tid = threadIdx.x;

    // ---- A loader: thread -> (kpair, oc, oc+32) ----
    const int kpA = tid & 7;
    const int ocA = tid >> 3;          // 0..31

    // ---- B loader: thread -> (pos, kpair base) ----
    const int posL = tid & 127;
    const int kpB  = tid >> 7;         // 0..1; kpairs kpB+2i
    const int posB = bn + posL;
    const int bbB  = posB / HW;
    const int rpB  = posB - bbB * HW;
    const int hoB  = rpB / Wout;
    const int woB  = rpB - hoB * Wout;
    const int hi0  = hoB * STRIDE - PAD;
    const int wi0  = woB * STRIDE - PAD;
    const float* xbase = x + ((size_t)bbB * CIN * Hin + hi0) * Win + wi0;

    float2 awR[2];
    float  bxR[8];

    auto loadA = [&](int k0) {
        const int k = k0 + 2 * kpA;
        #pragma unroll
        for (int i = 0; i < 2; i++) {
            const int oc = bm + ocA + 32 * i;
            const bool ok = (COUT % 64 == 0 || oc < COUT) && (K % 16 == 0 || k < K);
            if (KS == 1) {
                if (ok) awR[i] = *reinterpret_cast<const float2*>(&w[(size_t)oc * K + k]);
                else { awR[i].x = 0.f; awR[i].y = 0.f; }
            } else {
                const int p  = k / CIN;
                const int ic = k - p * CIN;
                const size_t off = (size_t)oc * K + ic * KSKS + p;
                awR[i].x = ok ? __ldg(&w[off]) : 0.f;
                awR[i].y = ok ? __ldg(&w[off + KSKS]) : 0.f;
            }
        }
    };

    auto loadB = [&](int k0) {
        if (KS == 1) {
            #pragma unroll
            for (int i = 0; i < 4; i++) {
                const int kp = kpB + 2 * i;
                #pragma unroll
                for (int j = 0; j < 2; j++) {
                    const int k = k0 + 2 * kp + j;
                    bxR[2 * i + j] = (K % 16 == 0 || k < K)
                        ? __ldg(&xbase[(size_t)k * HWin]) : 0.f;
                }
            }
        } else if (CIN % 16 == 0) {
            // whole tile shares one spatial tap p
            const int p  = k0 / CIN;
            const int kh = p / 3, kw = p - 3 * kh;
            const int hi = hi0 + kh, wi = wi0 + kw;
            const bool valid = (hi >= 0) & (hi < Hin) & (wi >= 0) & (wi < Win);
            const int ic0 = k0 - p * CIN;
            const float* bp = xbase + (size_t)ic0 * HWin + kh * Win + kw;
            #pragma unroll
            for (int i = 0; i < 4; i++) {
                const int kp = kpB + 2 * i;
                bxR[2 * i]     = valid ? __ldg(bp + (size_t)(2 * kp)     * HWin) : 0.f;
                bxR[2 * i + 1] = valid ? __ldg(bp + (size_t)(2 * kp + 1) * HWin) : 0.f;
            }
        } else {
            #pragma unroll
            for (int i = 0; i < 4; i++) {
                const int kp = kpB + 2 * i;
                #pragma unroll
                for (int j = 0; j < 2; j++) {
                    const int k = k0 + 2 * kp + j;
                    float v = 0.f;
                    if (k < K) {
                        const int p  = k / CIN;
                        const int ic = k - p * CIN;
                        const int kh = p / 3, kw = p - 3 * kh;
                        const int hi = hi0 + kh, wi = wi0 + kw;
                        if (hi >= 0 && hi < Hin && wi >= 0 && wi < Win)
                            v = __ldg(&xbase[(size_t)ic * HWin + kh * Win + kw]);
                    }
                    bxR[2 * i + j] = v;
                }
            }
        }
    };

    auto storeTile = [&](int buf) {
        #pragma unroll
        for (int i = 0; i < 2; i++)
            Ap[buf][kpA][ocA + 32 * i] = split2(awR[i].x, awR[i].y);
        #pragma unroll
        for (int i = 0; i < 4; i++)
            Bp[buf][kpB + 2 * i][posL] = split2(bxR[2 * i], bxR[2 * i + 1]);
    };

    // prologue
    loadA(0); loadB(0);
    storeTile(0);
    __syncthreads();

    // ---- compute mapping ----
    const int warp = tid >> 5, lane = tid & 31;
    const int wm = warp >> 2, wn = warp & 3;
    const int g  = lane >> 2, tg = lane & 3;

    float acc[2][4][4];
    #pragma unroll
    for (int mt = 0; mt < 2; mt++)
        #pragma unroll
        for (int nt = 0; nt < 4; nt++)
            #pragma unroll
            for (int r = 0; r < 4; r++) acc[mt][nt][r] = 0.f;

    for (int t = 0; t < NK; t++) {
        const int cur = t & 1, nxt = cur ^ 1;
        const bool more = (t + 1) < NK;
        if (more) { loadA((t + 1) << 4); loadB((t + 1) << 4); }

        uint32_t ah[2][4], al[2][4];
        #pragma unroll
        for (int mt = 0; mt < 2; mt++) {
            const int ob = wm * 32 + mt * 16 + g;
            const uint2 q0 = Ap[cur][tg    ][ob    ];
            const uint2 q1 = Ap[cur][tg    ][ob + 8];
            const uint2 q2 = Ap[cur][tg + 4][ob    ];
            const uint2 q3 = Ap[cur][tg + 4][ob + 8];
            ah[mt][0] = q0.x; ah[mt][1] = q1.x; ah[mt][2] = q2.x; ah[mt][3] = q3.x;
            al[mt][0] = q0.y; al[mt][1] = q1.y; al[mt][2] = q2.y; al[mt][3] = q3.y;
        }
        uint32_t bh[4][2], bl[4][2];
        #pragma unroll
        for (int nt = 0; nt < 4; nt++) {
            const int pb = wn * 32 + nt * 8 + g;
            const uint2 r0 = Bp[cur][tg    ][pb];
            const uint2 r1 = Bp[cur][tg + 4][pb];
            bh[nt][0] = r0.x; bh[nt][1] = r1.x;
            bl[nt][0] = r0.y; bl[nt][1] = r1.y;
        }
        #pragma unroll
        for (int mt = 0; mt < 2; mt++)
            #pragma unroll
            for (int nt = 0; nt < 4; nt++) {
                mma_bf16(acc[mt][nt], ah[mt], bh[nt]);
                mma_bf16(acc[mt][nt], ah[mt], bl[nt]);
                mma_bf16(acc[mt][nt], al[mt], bh[nt]);
            }

        if (more) {
            storeTile(nxt);
            __syncthreads();
        }
    }

    // ---- epilogue ----
    const int bb  = bn / HW;                 // whole block shares one batch
    const int rp0 = bn - bb * HW;

    #pragma unroll
    for (int mt = 0; mt < 2; mt++) {
        #pragma unroll
        for (int hf = 0; hf < 2; hf++) {
            const int oc = bm + wm * 32 + mt * 16 + g + hf * 8;
            if (!(COUT % 64 == 0) && oc >= COUT) continue;
            float scale = 1.f, bias = 0.f;
            if (DO_BN) {
                const float s = bn_g[oc] * rsqrtf(bn_v[oc] + 1e-5f);
                scale = s;
                bias  = bn_b[oc] - bn_m[oc] * s;
            }
            float* orow = out + (size_t)(bb * COUT + oc) * HW + rp0;
            #pragma unroll
            for (int nt = 0; nt < 4; nt++) {
                const int pc = wn * 32 + nt * 8 + 2 * tg;
                float v0 = acc[mt][nt][hf * 2 + 0];
                float v1 = acc[mt][nt][hf * 2 + 1];
                if (DO_BN) {
                    v0 = v0 * scale + bias;  v0 = (v0 >= 0.f) ? v0 : 0.1f * v0;
                    v1 = v1 * scale + bias;  v1 = (v1 >= 0.f) ? v1 : 0.1f * v1;
                }
                float2 vv; vv.x = v0; vv.y = v1;
                *reinterpret_cast<float2*>(&orow[pc]) = vv;
            }
        }
    }
}

// ---------------------------------------------------------------------------
// Fused: softmax over 9 logits per (b, group, ho, wo), then weighted unfold
// sum over the 3x3 stride-2 patch. Channel for (i, g) is ch = i*G + g.
// ---------------------------------------------------------------------------
__global__ void adaptive_ds_kernel(
    const float* __restrict__ x, const float* __restrict__ logits,
    float* __restrict__ out,
    int Cin, int G, int Hin, int Win, int Bsz)
{
    const int idx = blockIdx.x * blockDim.x + threadIdx.x;
    const int total = Bsz * G * HW_;
    if (idx >= total) return;

    const int wo = idx % WO_;
    int t = idx / WO_;
    const int ho = t % HO_;  t /= HO_;
    const int g  = t % G;
    const int b  = t / G;

    float lg[9];
    float mx = -1e30f;
    const size_t lbase = ((size_t)(b * G * 9 + g * 9) * HW_) + ho * WO_ + wo;
    #pragma unroll
    for (int k = 0; k < 9; k++) {
        lg[k] = logits[lbase + (size_t)k * HW_];
        mx = fmaxf(mx, lg[k]);
    }
    float s = 0.f;
    #pragma unroll
    for (int k = 0; k < 9; k++) { lg[k] = __expf(lg[k] - mx); s += lg[k]; }
    const float inv = 1.f / s;
    #pragma unroll
    for (int k = 0; k < 9; k++) lg[k] *= inv;

    const int cpg = Cin / G;
    for (int i = 0; i < cpg; i++) {
        const int ch = i * G + g;
        const float* xb = x + (size_t)(b * Cin + ch) * Hin * Win;
        float acc = 0.f;
        #pragma unroll
        for (int kh = 0; kh < 3; kh++) {
            const int hi = 2 * ho + kh - 1;
            if (hi < 0 || hi >= Hin) continue;
            #pragma unroll
            for (int kw = 0; kw < 3; kw++) {
                const int wi = 2 * wo + kw - 1;
                if (wi < 0 || wi >= Win) continue;
                acc += lg[kh * 3 + kw] * __ldg(&xb[(size_t)hi * Win + wi]);
            }
        }
        out[((size_t)(b * Cin + ch) * HW_) + ho * WO_ + wo] = acc;
    }
}

// ---------------------------------------------------------------------------
// Cost volumes. Output (2, 32, 24, 80, 144):
//   c in [0,8):   gwc corr  mean_{cc<12} l[g*12+cc][w] * r[g*12+cc][w-d]
//   c in [8,20):  l_c[c-8][w]       if w>=d else 0
//   c in [20,32): r_c[c-20][w-d]    if w>=d else 0
// ---------------------------------------------------------------------------
__global__ void build_volume_kernel(
    const float* __restrict__ g8x, const float* __restrict__ c8x,
    float* __restrict__ out)
{
    const int W = WO_, H = HO_, D = 24, OC = 32;
    const int total = 2 * OC * D * H * W;
    const int idx = blockIdx.x * blockDim.x + threadIdx.x;
    if (idx >= total) return;

    const int w = idx % W;
    int t = idx / W;
    const int h = t % H;  t /= H;
    const int d = t % D;  t /= D;
    const int c = t % OC;
    const int b = t / OC;

    float v = 0.f;
    if (c < 8) {
        if (w >= d) {
            const float* l = g8x + ((size_t)(b       * 96 + c * 12) * H + h) * W;
            const float* r = g8x + ((size_t)((b + 2) * 96 + c * 12) * H + h) * W;
            float acc = 0.f;
            #pragma unroll
            for (int cc = 0; cc < 12; cc++)
                acc += __ldg(&l[(size_t)cc * H * W + w]) * __ldg(&r[(size_t)cc * H * W + w - d]);
            v = acc * (1.f / 12.f);
        }
    } else if (c < 20) {
        const int ch = c - 8;
        if (w >= d) v = __ldg(&c8x[((size_t)(b * 12 + ch) * H + h) * W + w]);
    } else {
        const int ch = c - 20;
        if (w >= d) v = __ldg(&c8x[((size_t)((b + 2) * 12 + ch) * H + h) * W + w - d]);
    }
    out[idx] = v;
}

// ---------------------------------------------------------------------------
extern "C" void kernel_launch(void* const* d_in, const int* in_sizes, int n_in,
                              void* d_out, int out_size)
{
    const float* gwc = (const float*)d_in[0];
    const float* cat = (const float*)d_in[1];
    const float* gw1 = (const float*)d_in[2];
    const float* gbg = (const float*)d_in[3];
    const float* gbb = (const float*)d_in[4];
    const float* gbm = (const float*)d_in[5];
    const float* gbv = (const float*)d_in[6];
    const float* gw2 = (const float*)d_in[7];
    const float* cw1 = (const float*)d_in[8];
    const float* cbg = (const float*)d_in[9];
    const float* cbb = (const float*)d_in[10];
    const float* cbm = (const float*)d_in[11];
    const float* cbv = (const float*)d_in[12];
    const float* cw2 = (const float*)d_in[13];
    float* out = (float*)d_out;

    float *y1, *mask, *g8x, *cy1, *cmask, *c8x;
    cudaGetSymbolAddress((void**)&y1,    g_y1);
    cudaGetSymbolAddress((void**)&mask,  g_mask);
    cudaGetSymbolAddress((void**)&g8x,   g_g8x);
    cudaGetSymbolAddress((void**)&cy1,   g_cy1);
    cudaGetSymbolAddress((void**)&cmask, g_cmask);
    cudaGetSymbolAddress((void**)&c8x,   g_c8x);

    const int nTiles = (4 * HW_) / 128;   // 360 (exact)

    // gwc branch
    conv_mma_kernel<3, 96, 192, true><<<dim3(nTiles, 3), 256>>>(
        gwc, gw1, gbg, gbb, gbm, gbv, y1, 160, 288, HO_, WO_);
    conv_mma_kernel<1, 192, 144, false><<<dim3(nTiles, 3), 256>>>(
        y1, gw2, nullptr, nullptr, nullptr, nullptr, mask, HO_, WO_, HO_, WO_);
    adaptive_ds_kernel<<<(4 * 16 * HW_ + 255) / 256, 256>>>(
        gwc, mask, g8x, 96, 16, 160, 288, 4);

    // concat branch
    conv_mma_kernel<3, 12, 24, true><<<dim3(nTiles, 1), 256>>>(
        cat, cw1, cbg, cbb, cbm, cbv, cy1, 160, 288, HO_, WO_);
    conv_mma_kernel<1, 24, 108, false><<<dim3(nTiles, 2), 256>>>(
        cy1, cw2, nullptr, nullptr, nullptr, nullptr, cmask, HO_, WO_, HO_, WO_);
    adaptive_ds_kernel<<<(4 * 12 * HW_ + 255) / 256, 256>>>(
        cat, cmask, c8x, 12, 12, 160, 288, 4);

    // volumes -> d_out
    build_volume_kernel<<<(2 * 32 * 24 * HW_ + 255) / 256, 256>>>(g8x, c8x, out);
}